// round 2
// baseline (speedup 1.0000x reference)
#include <cuda_runtime.h>
#include <cuda_bf16.h>
#include <cstdint>

// Problem constants
#define BATCH 64
#define TSTEPS 2048
#define DIN 128
#define HID 256
#define DOUT 128
#define G4H (4*HID)        // 1024

// Scan tiling: 16 column-groups x 8 batch-groups = 128 CTAs
#define NCTA 128
#define JPC 16             // hidden units per CTA
#define NCOL 64            // gate columns per CTA (4 gates * 16)
#define BPC 8              // batches per CTA
#define KTOT (HID+DIN)     // 384 (h rows then x rows)
#define KC 96              // K per k-chunk (4 chunks)
#define NTHREADS 256

// padded SMEM strides (floats)
#define WSTR 388           // per-column stride for sW [c][k]
#define HSTR 392           // per-batch stride for sH [b][k]
#define PSTR 65            // partials stride

// SMEM layout (floats)
#define SM_W     0
#define SM_H     (SM_W + NCOL*WSTR)          // 24832
#define SM_PART  (SM_H + BPC*HSTR)           // +3136
#define SM_C     (SM_PART + 4*BPC*PSTR)      // +2080
#define SM_BIAS  (SM_C + JPC*BPC)            // +128
#define SM_FLOATS (SM_BIAS + NCOL)           // +64
#define SMEM_BYTES (SM_FLOATS*4)             // ~121 KB

// Global scratch (static; no allocations allowed)
__device__ __align__(16) float g_xT[(size_t)TSTEPS * DIN * BATCH]; // [t][d][b]
__device__ __align__(16) float g_h[2][HID * BATCH];                // [k][b] double buffer
__device__ unsigned g_ctr;

__device__ __forceinline__ uint32_t smem_u32(const void* p) {
    return (uint32_t)__cvta_generic_to_shared(p);
}

// ---------------------------------------------------------------------------
__global__ void init_kernel() {
    int i = blockIdx.x * blockDim.x + threadIdx.x;
    if (i == 0) g_ctr = 0u;
    if (i < HID * BATCH) g_h[0][i] = 0.0f;
}

// transpose x [b][t][d] -> g_xT [t][d][b]
__global__ void transpose_x_kernel(const float* __restrict__ x) {
    __shared__ float tile[BATCH][DIN + 1];
    int t = blockIdx.x;
    for (int i = threadIdx.x; i < BATCH * DIN; i += blockDim.x) {
        int b = i >> 7, d = i & 127;
        tile[b][d] = x[((size_t)b * TSTEPS + t) * DIN + d];
    }
    __syncthreads();
    float* dst = g_xT + (size_t)t * DIN * BATCH;
    for (int i = threadIdx.x; i < BATCH * DIN; i += blockDim.x) {
        int d = i >> 6, b = i & 63;
        dst[i] = tile[b][d];
    }
}

// ---------------------------------------------------------------------------
// persistent LSTM scan: CTA = (cg, bg) -> 16 hidden units x 8 batches
// ---------------------------------------------------------------------------
__global__ void __launch_bounds__(NTHREADS, 1)
lstm_scan_kernel(const float* __restrict__ W_x,
                 const float* __restrict__ W_h,
                 const float* __restrict__ bias) {
    extern __shared__ float smem[];
    float* sW    = smem + SM_W;     // [c][k] padded, c = gate*16 + lj
    float* sH    = smem + SM_H;     // [b][k] padded (k<256: h, k>=256: x)
    float* sPart = smem + SM_PART;  // [kc][b][c] padded
    float* sC    = smem + SM_C;     // [b*16 + lj]
    float* sBias = smem + SM_BIAS;  // [c]

    const int tid = threadIdx.x;
    const int cg  = blockIdx.x & 15;
    const int bg  = blockIdx.x >> 4;
    const int j0  = cg * JPC;

    // ---- stage weights once: sW[c][k]
    for (int idx = tid; idx < NCOL * KTOT; idx += NTHREADS) {
        int k = idx >> 6;            // /64
        int c = idx & 63;
        int gate = c >> 4, lj = c & 15;
        int gcol = gate * HID + j0 + lj;
        float w = (k < HID) ? W_h[(size_t)k * G4H + gcol]
                            : W_x[(size_t)(k - HID) * G4H + gcol];
        sW[c * WSTR + k] = w;
    }
    if (tid < NCOL) {
        int gate = tid >> 4, lj = tid & 15;
        sBias[tid] = bias[gate * HID + j0 + lj];
    }
    if (tid < JPC * BPC) sC[tid] = 0.0f;
    __syncthreads();

    // thread decode for compute: cq in [0,8), b in [0,8), kc in [0,4)
    const int cq = tid & 7;
    const int b  = (tid >> 3) & 7;
    const int kc = tid >> 6;
    const int k0 = kc * KC;

    const uint32_t haddr0 = smem_u32(sH + b * HSTR + k0);
    const uint32_t waddr0 = smem_u32(sW + cq * WSTR + k0);

    // staging decode
    const int kstage = tid;           // h row to stage
    const int d      = tid >> 1;      // x row
    const int half   = tid & 1;

    for (int s = 0; s < TSTEPS; s++) {
        const int rbuf = s & 1;

        // ---- prefetch x_t slice into registers (independent of barrier)
        float4 xv = __ldg(reinterpret_cast<const float4*>(
            g_xT + ((size_t)s * DIN + d) * BATCH + bg * BPC) + half);

        // ---- wait for all CTAs to have finished step s-1
        if (s > 0) {
            __syncthreads();
            if (tid == 0) {
                unsigned target = (unsigned)NCTA * (unsigned)s;
                unsigned v;
                do {
                    asm volatile("ld.acquire.gpu.global.u32 %0, [%1];"
                                 : "=r"(v) : "l"(&g_ctr) : "memory");
                } while (v < target);
            }
            __syncthreads();
        }

        // ---- stage h (8 floats, this CTA's batches) and x regs into sH[b][k]
        {
            const float4* hs = reinterpret_cast<const float4*>(
                g_h[rbuf] + kstage * BATCH + bg * BPC);
            float4 a0 = __ldcg(hs);
            float4 a1 = __ldcg(hs + 1);
            sH[0 * HSTR + kstage] = a0.x;
            sH[1 * HSTR + kstage] = a0.y;
            sH[2 * HSTR + kstage] = a0.z;
            sH[3 * HSTR + kstage] = a0.w;
            sH[4 * HSTR + kstage] = a1.x;
            sH[5 * HSTR + kstage] = a1.y;
            sH[6 * HSTR + kstage] = a1.z;
            sH[7 * HSTR + kstage] = a1.w;
            int bb = 4 * half;
            sH[(bb + 0) * HSTR + HID + d] = xv.x;
            sH[(bb + 1) * HSTR + HID + d] = xv.y;
            sH[(bb + 2) * HSTR + HID + d] = xv.z;
            sH[(bb + 3) * HSTR + HID + d] = xv.w;
        }
        __syncthreads();

        // ---- partial GEMM: 8 cols (c = cq + 8q) x 1 batch x KC, f32x2 along K
        unsigned long long acc[8];
        #pragma unroll
        for (int q = 0; q < 8; q++) acc[q] = 0ull;

        #pragma unroll
        for (int kk = 0; kk < KC; kk += 4) {
            unsigned long long h01, h23;
            asm volatile("ld.shared.v2.u64 {%0,%1}, [%2];"
                         : "=l"(h01), "=l"(h23)
                         : "r"(haddr0 + kk * 4));
            #pragma unroll
            for (int q = 0; q < 8; q++) {
                unsigned long long w01, w23;
                asm volatile("ld.shared.v2.u64 {%0,%1}, [%2];"
                             : "=l"(w01), "=l"(w23)
                             : "r"(waddr0 + (q * (8 * WSTR) + kk) * 4));
                asm volatile("fma.rn.f32x2 %0, %1, %2, %0;"
                             : "+l"(acc[q]) : "l"(h01), "l"(w01));
                asm volatile("fma.rn.f32x2 %0, %1, %2, %0;"
                             : "+l"(acc[q]) : "l"(h23), "l"(w23));
            }
        }

        // ---- horizontal add + write partials
        #pragma unroll
        for (int q = 0; q < 8; q++) {
            float lo, hi;
            asm("mov.b64 {%0,%1}, %2;" : "=f"(lo), "=f"(hi) : "l"(acc[q]));
            sPart[(kc * BPC + b) * PSTR + cq + 8 * q] = lo + hi;
        }
        __syncthreads();

        // ---- epilogue: 128 threads = (b, lj); reduce 4 partials, activations
        if (tid < JPC * BPC) {
            int bb = tid >> 4;
            int lj = tid & 15;
            float g4[4];
            #pragma unroll
            for (int gate = 0; gate < 4; gate++) {
                int c = gate * JPC + lj;
                float v = sBias[c];
                #pragma unroll
                for (int q = 0; q < 4; q++)
                    v += sPart[(q * BPC + bb) * PSTR + c];
                g4[gate] = v;
            }
            float ig = 1.0f / (1.0f + __expf(-g4[0]));
            float fg = 1.0f / (1.0f + __expf(-g4[1]));
            float gg = tanhf(g4[2]);
            float og = 1.0f / (1.0f + __expf(-g4[3]));
            float cnew = fg * sC[tid] + ig * gg;
            sC[tid] = cnew;
            float hnew = og * tanhf(cnew);
            __stcg(&g_h[rbuf ^ 1][(j0 + lj) * BATCH + bg * BPC + bb], hnew);
        }
        __syncthreads();

        // ---- arrive (release the h writes)
        if (tid == 0) {
            __threadfence();
            asm volatile("red.relaxed.gpu.global.add.u32 [%0], %1;"
                         :: "l"(&g_ctr), "r"(1u) : "memory");
        }
    }
}

// ---------------------------------------------------------------------------
// final FC: out[b][d] = sum_k h_final[k][b] * fc_w[k][d] + fc_b[d]
// after 2048 steps, final h is in g_h[0]
// ---------------------------------------------------------------------------
__global__ void fc_kernel(const float* __restrict__ fc_w,
                          const float* __restrict__ fc_b,
                          float* __restrict__ out) {
    int b = blockIdx.x;
    int d = threadIdx.x;
    const float* hf = g_h[0];
    float acc = fc_b[d];
    #pragma unroll 8
    for (int k = 0; k < HID; k++)
        acc += hf[k * BATCH + b] * fc_w[k * DOUT + d];
    out[b * DOUT + d] = acc;
}

// ---------------------------------------------------------------------------
extern "C" void kernel_launch(void* const* d_in, const int* in_sizes, int n_in,
                              void* d_out, int out_size) {
    const float* x    = (const float*)d_in[0];
    const float* W_x  = (const float*)d_in[1];
    const float* W_h  = (const float*)d_in[2];
    const float* bvec = (const float*)d_in[3];
    const float* fc_w = (const float*)d_in[4];
    const float* fc_b = (const float*)d_in[5];
    float* out = (float*)d_out;

    cudaFuncSetAttribute(lstm_scan_kernel,
                         cudaFuncAttributeMaxDynamicSharedMemorySize, SMEM_BYTES);

    init_kernel<<<(HID * BATCH + 255) / 256, 256>>>();
    transpose_x_kernel<<<TSTEPS, 256>>>(x);
    lstm_scan_kernel<<<NCTA, NTHREADS, SMEM_BYTES>>>(W_x, W_h, bvec);
    fc_kernel<<<BATCH, DOUT>>>(fc_w, fc_b, out);
}

// round 3
// speedup vs baseline: 1.7341x; 1.7341x over previous
#include <cuda_runtime.h>
#include <cuda_bf16.h>
#include <cstdint>

// Problem constants
#define BATCH 64
#define TSTEPS 2048
#define DIN 128
#define HID 256
#define DOUT 128
#define G4H (4*HID)        // 1024

// Tiling: 16 column-groups x 8 batch-groups = 128 CTAs
#define NCTA 128
#define JPC 16             // hidden units per CTA
#define NCOL 64            // gate columns per CTA
#define BPC 8              // batches per CTA
#define KTOT (HID+DIN)     // 384
#define KC 48              // K per k-chunk (8 chunks = 8 warps)
#define NTHREADS 256

// padded SMEM strides (floats)
#define WSTR 388           // sW [c][k]   (388*4 mod 128 = 16 -> cq spread)
#define HSTR 388           // sH [b][k]   (b spread 16B apart)
#define PSTR 68            // sPart inner (bank = 4b + c, conflict-free)

#define SM_W     0
#define SM_H     (SM_W + NCOL*WSTR)           // 24832
#define SM_PART  (SM_H + BPC*HSTR)            // +3104
#define SM_C     (SM_PART + 8*BPC*PSTR)       // +4352
#define SM_BIAS  (SM_C + JPC*BPC)             // +128
#define SM_FLOATS (SM_BIAS + NCOL)
#define SMEM_BYTES (SM_FLOATS*4)              // ~130 KB

// Global scratch
__device__ __align__(16) float g_xT[(size_t)TSTEPS * DIN * BATCH];  // [t][d][b]
__device__ __align__(16) float g_h[2][8][HID * BPC];                // [buf][bg][j*8+bb]
__device__ unsigned g_ctrs[8 * 256];                                // per-bg, 1KB apart

__device__ __forceinline__ uint32_t smem_u32(const void* p) {
    return (uint32_t)__cvta_generic_to_shared(p);
}
__device__ __forceinline__ float fast_sig(float x) {
    return __fdividef(1.0f, 1.0f + __expf(-x));
}
__device__ __forceinline__ float fast_tanh(float x) {
    return __fdividef(2.0f, 1.0f + __expf(-2.0f * x)) - 1.0f;
}

// ---------------------------------------------------------------------------
__global__ void init_kernel() {
    int i = blockIdx.x * blockDim.x + threadIdx.x;
    if (i < 8 * 256) g_ctrs[i] = 0u;
    if (i < HID * BATCH) ((float*)g_h[0])[i] = 0.0f;
}

// transpose x [b][t][d] -> g_xT [t][d][b]
__global__ void transpose_x_kernel(const float* __restrict__ x) {
    __shared__ float tile[BATCH][DIN + 1];
    int t = blockIdx.x;
    for (int i = threadIdx.x; i < BATCH * DIN; i += blockDim.x) {
        int b = i >> 7, d = i & 127;
        tile[b][d] = x[((size_t)b * TSTEPS + t) * DIN + d];
    }
    __syncthreads();
    float* dst = g_xT + (size_t)t * DIN * BATCH;
    for (int i = threadIdx.x; i < BATCH * DIN; i += blockDim.x) {
        int d = i >> 6, b = i & 63;
        dst[i] = tile[b][d];
    }
}

// ---------------------------------------------------------------------------
// persistent LSTM scan: CTA = (cg, bg); sync only within the 16-CTA bg group
// ---------------------------------------------------------------------------
__global__ void __launch_bounds__(NTHREADS, 1)
lstm_scan_kernel(const float* __restrict__ W_x,
                 const float* __restrict__ W_h,
                 const float* __restrict__ bias) {
    extern __shared__ float smem[];
    float* sW    = smem + SM_W;     // [c][k], c = gate*16 + lj
    float* sH    = smem + SM_H;     // [b][k]  (k<256: h, k>=256: x)
    float* sPart = smem + SM_PART;  // [kc][b][c] stride PSTR
    float* sC    = smem + SM_C;     // [lj*8 + bb]
    float* sBias = smem + SM_BIAS;

    const int tid = threadIdx.x;
    const int cg  = blockIdx.x & 15;
    const int bg  = blockIdx.x >> 4;
    const int j0  = cg * JPC;
    unsigned* ctr = &g_ctrs[bg * 256];

    // ---- stage weights once: sW[c][k]
    for (int idx = tid; idx < NCOL * KTOT; idx += NTHREADS) {
        int k = idx >> 6, c = idx & 63;
        int gate = c >> 4, lj = c & 15;
        int gcol = gate * HID + j0 + lj;
        float w = (k < HID) ? W_h[(size_t)k * G4H + gcol]
                            : W_x[(size_t)(k - HID) * G4H + gcol];
        sW[c * WSTR + k] = w;
    }
    if (tid < NCOL) {
        int gate = tid >> 4, lj = tid & 15;
        sBias[tid] = bias[gate * HID + j0 + lj];
    }
    if (tid < JPC * BPC) sC[tid] = 0.0f;
    __syncthreads();

    // compute decode: 8 cq x 4 batch-pairs x 8 k-chunks
    const int lane = tid & 31;
    const int cq   = lane & 7;
    const int bp   = lane >> 3;          // 0..3
    const int kc   = tid >> 5;           // warp id = k-chunk
    const int k0   = kc * KC;

    const uint32_t haddr0 = smem_u32(sH + (2 * bp) * HSTR + k0);
    const uint32_t haddr1 = smem_u32(sH + (2 * bp + 1) * HSTR + k0);
    const uint32_t waddr  = smem_u32(sW + cq * WSTR + k0);

    // staging decode
    const int d    = tid >> 1;           // x row
    const int half = tid & 1;

    for (int s = 0; s < TSTEPS; s++) {
        const int rbuf = s & 1;

        // ---- prefetch x_t slice (independent of sync)
        float4 xv = __ldg(reinterpret_cast<const float4*>(
            g_xT + ((size_t)s * DIN + d) * BATCH + bg * BPC) + half);

        // ---- wait: all 16 CTAs of this bg finished step s-1
        if (s > 0) {
            if (tid == 0) {
                unsigned target = 16u * (unsigned)s, v;
                do {
                    asm volatile("ld.acquire.gpu.global.u32 %0, [%1];"
                                 : "=r"(v) : "l"(ctr) : "memory");
                } while (v < target);
            }
            __syncthreads();
        }

        // ---- stage h: contiguous 8KB -> sH[b][k] (transposing)
        {
            const float4* src = reinterpret_cast<const float4*>(g_h[rbuf][bg]);
            #pragma unroll
            for (int i = 0; i < 2; i++) {
                int idx = tid + i * NTHREADS;       // 0..511
                float4 v = __ldcg(src + idx);
                int k  = idx >> 1;
                int b0 = (idx & 1) * 4;
                sH[(b0 + 0) * HSTR + k] = v.x;
                sH[(b0 + 1) * HSTR + k] = v.y;
                sH[(b0 + 2) * HSTR + k] = v.z;
                sH[(b0 + 3) * HSTR + k] = v.w;
            }
            int b0 = 4 * half;
            sH[(b0 + 0) * HSTR + HID + d] = xv.x;
            sH[(b0 + 1) * HSTR + HID + d] = xv.y;
            sH[(b0 + 2) * HSTR + HID + d] = xv.z;
            sH[(b0 + 3) * HSTR + HID + d] = xv.w;
        }
        __syncthreads();

        // ---- partial GEMM: 8 cols x 2 batches x KC, f32x2 along K
        unsigned long long a0[8], a1[8];
        #pragma unroll
        for (int q = 0; q < 8; q++) { a0[q] = 0ull; a1[q] = 0ull; }

        #pragma unroll
        for (int kk = 0; kk < KC; kk += 4) {
            unsigned long long h01a, h23a, h01b, h23b;
            asm volatile("ld.shared.v2.u64 {%0,%1}, [%2];"
                         : "=l"(h01a), "=l"(h23a) : "r"(haddr0 + kk * 4));
            asm volatile("ld.shared.v2.u64 {%0,%1}, [%2];"
                         : "=l"(h01b), "=l"(h23b) : "r"(haddr1 + kk * 4));
            #pragma unroll
            for (int q = 0; q < 8; q++) {
                unsigned long long w01, w23;
                asm volatile("ld.shared.v2.u64 {%0,%1}, [%2];"
                             : "=l"(w01), "=l"(w23)
                             : "r"(waddr + (q * (8 * WSTR) + kk) * 4));
                asm volatile("fma.rn.f32x2 %0, %1, %2, %0;"
                             : "+l"(a0[q]) : "l"(h01a), "l"(w01));
                asm volatile("fma.rn.f32x2 %0, %1, %2, %0;"
                             : "+l"(a0[q]) : "l"(h23a), "l"(w23));
                asm volatile("fma.rn.f32x2 %0, %1, %2, %0;"
                             : "+l"(a1[q]) : "l"(h01b), "l"(w01));
                asm volatile("fma.rn.f32x2 %0, %1, %2, %0;"
                             : "+l"(a1[q]) : "l"(h23b), "l"(w23));
            }
        }

        // ---- horizontal add + partials (conflict-free: bank = 4b + c)
        #pragma unroll
        for (int q = 0; q < 8; q++) {
            int c = cq + 8 * q;
            float lo, hi;
            asm("mov.b64 {%0,%1}, %2;" : "=f"(lo), "=f"(hi) : "l"(a0[q]));
            sPart[(kc * BPC + 2 * bp) * PSTR + c] = lo + hi;
            asm("mov.b64 {%0,%1}, %2;" : "=f"(lo), "=f"(hi) : "l"(a1[q]));
            sPart[(kc * BPC + 2 * bp + 1) * PSTR + c] = lo + hi;
        }
        __syncthreads();

        // ---- epilogue: 128 threads = (lj, bb)
        if (tid < JPC * BPC) {
            int lj = tid >> 3;
            int bb = tid & 7;
            float g4[4];
            #pragma unroll
            for (int gate = 0; gate < 4; gate++) {
                int c = gate * JPC + lj;
                float v = sBias[c];
                #pragma unroll
                for (int q = 0; q < 8; q++)
                    v += sPart[(q * BPC + bb) * PSTR + c];
                g4[gate] = v;
            }
            float ig = fast_sig(g4[0]);
            float fg = fast_sig(g4[1]);
            float gg = fast_tanh(g4[2]);
            float og = fast_sig(g4[3]);
            float cnew = fg * sC[tid] + ig * gg;
            sC[tid] = cnew;
            float hnew = og * fast_tanh(cnew);
            // coalesced 512B burst per CTA
            __stcg(&g_h[rbuf ^ 1][bg][j0 * BPC + tid], hnew);
        }
        __syncthreads();

        // ---- arrive (release pairs with consumers' acquire)
        if (tid == 0) {
            asm volatile("red.release.gpu.global.add.u32 [%0], %1;"
                         :: "l"(ctr), "r"(1u) : "memory");
        }
    }
}

// ---------------------------------------------------------------------------
// final FC: out[b][d] = sum_k h_final[k][b] * fc_w[k][d] + fc_b[d]
// final h in g_h[0][bg][k*8+bb]
// ---------------------------------------------------------------------------
__global__ void fc_kernel(const float* __restrict__ fc_w,
                          const float* __restrict__ fc_b,
                          float* __restrict__ out) {
    int b = blockIdx.x;
    int d = threadIdx.x;
    const float* hf = g_h[0][b >> 3];
    int bb = b & 7;
    float acc = fc_b[d];
    #pragma unroll 8
    for (int k = 0; k < HID; k++)
        acc += hf[k * BPC + bb] * fc_w[k * DOUT + d];
    out[b * DOUT + d] = acc;
}

// ---------------------------------------------------------------------------
extern "C" void kernel_launch(void* const* d_in, const int* in_sizes, int n_in,
                              void* d_out, int out_size) {
    const float* x    = (const float*)d_in[0];
    const float* W_x  = (const float*)d_in[1];
    const float* W_h  = (const float*)d_in[2];
    const float* bvec = (const float*)d_in[3];
    const float* fc_w = (const float*)d_in[4];
    const float* fc_b = (const float*)d_in[5];
    float* out = (float*)d_out;

    cudaFuncSetAttribute(lstm_scan_kernel,
                         cudaFuncAttributeMaxDynamicSharedMemorySize, SMEM_BYTES);

    init_kernel<<<(HID * BATCH + 255) / 256, 256>>>();
    transpose_x_kernel<<<TSTEPS, 256>>>(x);
    lstm_scan_kernel<<<NCTA, NTHREADS, SMEM_BYTES>>>(W_x, W_h, bvec);
    fc_kernel<<<BATCH, DOUT>>>(fc_w, fc_b, out);
}